// round 9
// baseline (speedup 1.0000x reference)
#include <cuda_runtime.h>
#include <cuda_bf16.h>
#include <cfloat>
#include <math.h>

#define VOC   32000
#define EMB   512
#define HID   1024
#define BATCH 16
#define SEQ   256
#define G4    4096
#define ROWS  4096   // B*S

// ------------------------------- device scratch ---------------------------
__device__ float g_X[ROWS * EMB];
__device__ float g_A[ROWS * G4];
__device__ float g_h1seq[ROWS * HID];   // rows r = s*16+b
__device__ float g_h2seq[ROWS * HID];   // rows r = b*256+s
__device__ float g_h[2 * BATCH * HID];
__device__ float g_c[BATCH * HID];
__device__ float g_lse[ROWS];
__device__ float g_bias[2 * G4];
__device__ int   g_is64;

// ------------------------------- small kernels ----------------------------
__global__ void zero_k(float* p, int n) {
    int i = blockIdx.x * 256 + threadIdx.x;
    if (i < n) p[i] = 0.f;
}

__global__ void detect_i64(const unsigned int* p) {
    __shared__ int any;
    if (threadIdx.x == 0) any = 0;
    __syncthreads();
    int loc = 0;
    for (int i = threadIdx.x; i < 2048; i += 256) loc |= (p[2 * i + 1] != 0u);
    if (loc) atomicOr(&any, 1);
    __syncthreads();
    if (threadIdx.x == 0) g_is64 = (any == 0) ? 1 : 0;
}

__global__ void combine_bias(const float* __restrict__ a1, const float* __restrict__ a2,
                             const float* __restrict__ b1, const float* __restrict__ b2) {
    int i = blockIdx.x * 256 + threadIdx.x;
    if (i < G4) { g_bias[i] = a1[i] + a2[i]; g_bias[G4 + i] = b1[i] + b2[i]; }
}

__global__ void gather_x(const void* __restrict__ inp, const float* __restrict__ emb) {
    int idx4 = blockIdx.x * 256 + threadIdx.x;        // ROWS*128
    if (idx4 >= ROWS * (EMB / 4)) return;
    int r = idx4 >> 7, e4 = idx4 & 127;
    int s = r >> 4, b = r & 15;
    int pos = b * SEQ + s;
    int tok = g_is64 ? (int)((const long long*)inp)[pos] : ((const int*)inp)[pos];
    reinterpret_cast<float4*>(g_X)[idx4] =
        reinterpret_cast<const float4*>(emb)[(size_t)tok * 128 + e4];
}

// ------------------------------- SGEMM NT ---------------------------------
// C[m][n] = sum_k A[m*K+k]*B[n*K+k] + bias[n]; tile 128x128, 8x8/thread
__global__ void __launch_bounds__(256, 2) gemm_nt(
    const float* __restrict__ A, const float* __restrict__ B, float* __restrict__ C,
    int M, int N, int K, const float* __restrict__ bias)
{
    __shared__ __align__(16) float As[16][132];
    __shared__ __align__(16) float Bs[16][132];
    const int tid = threadIdx.x;
    const int n0 = blockIdx.x * 128, m0 = blockIdx.y * 128;
    const int tx = tid & 15, ty = tid >> 4;
    const int lr = tid >> 1, lk = (tid & 1) * 8;

    float acc[8][8];
#pragma unroll
    for (int i = 0; i < 8; i++)
#pragma unroll
        for (int j = 0; j < 8; j++) acc[i][j] = 0.f;

    const float* Ap = A + (size_t)(m0 + lr) * K + lk;
    const float* Bp = B + (size_t)(n0 + lr) * K + lk;

    for (int k0 = 0; k0 < K; k0 += 16) {
        float4 a0 = *reinterpret_cast<const float4*>(Ap + k0);
        float4 a1 = *reinterpret_cast<const float4*>(Ap + k0 + 4);
        float4 b0 = *reinterpret_cast<const float4*>(Bp + k0);
        float4 b1 = *reinterpret_cast<const float4*>(Bp + k0 + 4);
        __syncthreads();
        As[lk+0][lr]=a0.x; As[lk+1][lr]=a0.y; As[lk+2][lr]=a0.z; As[lk+3][lr]=a0.w;
        As[lk+4][lr]=a1.x; As[lk+5][lr]=a1.y; As[lk+6][lr]=a1.z; As[lk+7][lr]=a1.w;
        Bs[lk+0][lr]=b0.x; Bs[lk+1][lr]=b0.y; Bs[lk+2][lr]=b0.z; Bs[lk+3][lr]=b0.w;
        Bs[lk+4][lr]=b1.x; Bs[lk+5][lr]=b1.y; Bs[lk+6][lr]=b1.z; Bs[lk+7][lr]=b1.w;
        __syncthreads();
#pragma unroll
        for (int kk = 0; kk < 16; ++kk) {
            float4 t0 = *reinterpret_cast<const float4*>(&As[kk][ty * 4]);
            float4 t1 = *reinterpret_cast<const float4*>(&As[kk][64 + ty * 4]);
            float4 u0 = *reinterpret_cast<const float4*>(&Bs[kk][tx * 4]);
            float4 u1 = *reinterpret_cast<const float4*>(&Bs[kk][64 + tx * 4]);
            float a[8] = { t0.x,t0.y,t0.z,t0.w, t1.x,t1.y,t1.z,t1.w };
            float b[8] = { u0.x,u0.y,u0.z,u0.w, u1.x,u1.y,u1.z,u1.w };
#pragma unroll
            for (int i = 0; i < 8; i++)
#pragma unroll
                for (int j = 0; j < 8; j++)
                    acc[i][j] = fmaf(a[i], b[j], acc[i][j]);
        }
    }

    float bn[8];
#pragma unroll
    for (int j = 0; j < 8; j++)
        bn[j] = bias ? bias[n0 + (j >> 2) * 64 + tx * 4 + (j & 3)] : 0.f;
#pragma unroll
    for (int i = 0; i < 8; i++) {
        int m = m0 + (i >> 2) * 64 + ty * 4 + (i & 3);
        float4 v0 = make_float4(acc[i][0]+bn[0], acc[i][1]+bn[1], acc[i][2]+bn[2], acc[i][3]+bn[3]);
        float4 v1 = make_float4(acc[i][4]+bn[4], acc[i][5]+bn[5], acc[i][6]+bn[6], acc[i][7]+bn[7]);
        *reinterpret_cast<float4*>(&C[(size_t)m * N + n0 + tx * 4]) = v0;
        *reinterpret_cast<float4*>(&C[(size_t)m * N + n0 + 64 + tx * 4]) = v1;
    }
}

// ------------------------------- LSTM cell --------------------------------
// One (layer, step). CTA owns 8 hidden units (=> 32 Whh rows across 4 gates).
// 256 thr = 8 k-slices x 32 lanes; lane = rg*4+bg; thread does 4 rows x 4
// batches over 128 k; smem tree-reduce; 128-thread pointwise epilogue.
#define H_STRIDE 1028
#define CELL_SMEM ((16 * H_STRIDE + 256 * 16 + 32 * 16) * 4)

__global__ void __launch_bounds__(256) lstm_cell(
    const float* __restrict__ preg, const float* __restrict__ Whh,
    const float* __restrict__ h_in, float* __restrict__ h_out,
    float* __restrict__ c, float* __restrict__ seq_out, int seq_bstride)
{
    extern __shared__ float smem[];
    float* h_sm = smem;                       // 16 * H_STRIDE
    float* red  = smem + 16 * H_STRIDE;       // 256 * 16
    float* g_sm = red + 256 * 16;             // 32 * 16

    const int tid = threadIdx.x, cta = blockIdx.x;

    for (int t = tid; t < BATCH * (HID / 4); t += 256) {
        int b = t >> 8, k4 = t & 255;
        *reinterpret_cast<float4*>(&h_sm[b * H_STRIDE + k4 * 4]) =
            reinterpret_cast<const float4*>(h_in)[b * 256 + k4];
    }
    __syncthreads();

    const int ks = tid >> 5, lane = tid & 31;
    const int rg = lane >> 2, bg = lane & 3;
    const int gate = rg >> 1, jl0 = (rg & 1) * 4;
    const int grow0 = gate * HID + cta * 8 + jl0;

    const float* wp[4];
#pragma unroll
    for (int r = 0; r < 4; r++) wp[r] = Whh + (size_t)(grow0 + r) * HID + ks * 128;
    const float* hq[4];
#pragma unroll
    for (int q = 0; q < 4; q++) hq[q] = &h_sm[(bg + 4 * q) * H_STRIDE + ks * 128];

    float acc[16];
#pragma unroll
    for (int q = 0; q < 16; q++) acc[q] = 0.f;

#pragma unroll 4
    for (int kk = 0; kk < 128; kk += 4) {
        float4 wv[4], hv[4];
#pragma unroll
        for (int r = 0; r < 4; r++) wv[r] = *reinterpret_cast<const float4*>(wp[r] + kk);
#pragma unroll
        for (int q = 0; q < 4; q++) hv[q] = *reinterpret_cast<const float4*>(hq[q] + kk);
#pragma unroll
        for (int r = 0; r < 4; r++)
#pragma unroll
            for (int q = 0; q < 4; q++) {
                float s = acc[r * 4 + q];
                s = fmaf(wv[r].x, hv[q].x, s);
                s = fmaf(wv[r].y, hv[q].y, s);
                s = fmaf(wv[r].z, hv[q].z, s);
                s = fmaf(wv[r].w, hv[q].w, s);
                acc[r * 4 + q] = s;
            }
    }

#pragma unroll
    for (int q = 0; q < 16; q++) red[tid * 16 + q] = acc[q];
    __syncthreads();

    if (tid < 32) {
        int trg = tid >> 2, tbg = tid & 3;
        int tgate = trg >> 1, tjl0 = (trg & 1) * 4;
#pragma unroll
        for (int rr = 0; rr < 4; rr++) {
            int grow = tgate * HID + cta * 8 + tjl0 + rr;
            int lrow = trg * 4 + rr;
#pragma unroll
            for (int bb = 0; bb < 4; bb++) {
                int b = tbg + 4 * bb;
                float sum = 0.f;
#pragma unroll
                for (int p = 0; p < 8; p++) sum += red[(p * 32 + tid) * 16 + rr * 4 + bb];
                g_sm[lrow * 16 + b] = sum + preg[b * G4 + grow];
            }
        }
    }
    __syncthreads();

    if (tid < 128) {
        int jl = tid & 7, b = tid >> 3;
        float iv = g_sm[(0 + jl) * 16 + b];
        float fv = g_sm[(8 + jl) * 16 + b];
        float gv = g_sm[(16 + jl) * 16 + b];
        float ov = g_sm[(24 + jl) * 16 + b];
        int idx = b * HID + cta * 8 + jl;
        float si = 1.f / (1.f + expf(-iv));
        float sf = 1.f / (1.f + expf(-fv));
        float so = 1.f / (1.f + expf(-ov));
        float cn = sf * c[idx] + si * tanhf(gv);
        float hn = so * tanhf(cn);
        c[idx] = cn;
        h_out[idx] = hn;
        seq_out[b * seq_bstride + cta * 8 + jl] = hn;
    }
}

// ------------------------------- log-softmax ------------------------------
__device__ __forceinline__ float fast_exp_neg(float x) {   // x <= 0
    x = fmaxf(x, -87.0f);
    float t = x * 1.4426950408889634f;
    float fl = floorf(t);
    float r = t - fl;
    float p = 1.5403530393381609e-4f;
    p = fmaf(p, r, 1.3333558146428443e-3f);
    p = fmaf(p, r, 9.6181291076284772e-3f);
    p = fmaf(p, r, 5.5504108664821580e-2f);
    p = fmaf(p, r, 2.4022650695910072e-1f);
    p = fmaf(p, r, 6.9314718055994531e-1f);
    p = fmaf(p, r, 1.0f);
    return p * __int_as_float(((int)fl + 127) << 23);
}

__global__ void lse_kernel(const float* __restrict__ logits, float* __restrict__ lse) {
    __shared__ float sm[256], ss[256];
    const int row = blockIdx.x, tid = threadIdx.x;
    const float4* base = reinterpret_cast<const float4*>(logits + (size_t)row * VOC);
    float m = -FLT_MAX, s = 0.f;
    for (int i = tid; i < VOC / 4; i += 256) {
        float4 v = base[i];
        float xs[4] = { v.x, v.y, v.z, v.w };
#pragma unroll
        for (int q = 0; q < 4; q++) {
            float x = xs[q];
            if (x > m) { s = s * fast_exp_neg(m - x) + 1.f; m = x; }
            else       { s += fast_exp_neg(x - m); }
        }
    }
    sm[tid] = m; ss[tid] = s;
    __syncthreads();
    for (int off = 128; off; off >>= 1) {
        if (tid < off) {
            float m1 = sm[tid], s1 = ss[tid], m2 = sm[tid + off], s2 = ss[tid + off];
            float mm = fmaxf(m1, m2);
            ss[tid] = s1 * fast_exp_neg(m1 - mm) + s2 * fast_exp_neg(m2 - mm);
            sm[tid] = mm;
        }
        __syncthreads();
    }
    if (tid == 0) lse[row] = sm[0] + logf(ss[0]);
}

__global__ void sub_kernel(float* __restrict__ out, const float* __restrict__ lse) {
    int idx4 = blockIdx.x * 256 + threadIdx.x;   // ROWS*(VOC/4)
    int row = idx4 / (VOC / 4);
    float l = lse[row];
    float4* p = reinterpret_cast<float4*>(out) + idx4;
    float4 v = *p;
    v.x -= l; v.y -= l; v.z -= l; v.w -= l;
    *p = v;
}

// ------------------------------- launcher ---------------------------------
extern "C" void kernel_launch(void* const* d_in, const int* in_sizes, int n_in,
                              void* d_out, int out_size) {
    (void)in_sizes; (void)n_in; (void)out_size;
    const void*  inp   = d_in[0];
    const float* emb   = (const float*)d_in[1];
    const float* W_ih1 = (const float*)d_in[2];
    const float* W_hh1 = (const float*)d_in[3];
    const float* b_ih1 = (const float*)d_in[4];
    const float* b_hh1 = (const float*)d_in[5];
    const float* W_ih2 = (const float*)d_in[6];
    const float* W_hh2 = (const float*)d_in[7];
    const float* b_ih2 = (const float*)d_in[8];
    const float* b_hh2 = (const float*)d_in[9];
    const float* W_log = (const float*)d_in[10];
    const float* b_log = (const float*)d_in[11];
    float* out = (float*)d_out;

    static bool attr_set = false;
    if (!attr_set) {
        cudaFuncSetAttribute(lstm_cell, cudaFuncAttributeMaxDynamicSharedMemorySize, CELL_SMEM);
        attr_set = true;
    }

    float *X, *A, *h1s, *h2s, *h, *c, *lse;
    cudaGetSymbolAddress((void**)&X,   g_X);
    cudaGetSymbolAddress((void**)&A,   g_A);
    cudaGetSymbolAddress((void**)&h1s, g_h1seq);
    cudaGetSymbolAddress((void**)&h2s, g_h2seq);
    cudaGetSymbolAddress((void**)&h,   g_h);
    cudaGetSymbolAddress((void**)&c,   g_c);
    cudaGetSymbolAddress((void**)&lse, g_lse);
    float* bias;
    cudaGetSymbolAddress((void**)&bias, g_bias);

    detect_i64<<<1, 256>>>((const unsigned int*)inp);
    combine_bias<<<16, 256>>>(b_ih1, b_hh1, b_ih2, b_hh2);
    gather_x<<<2048, 256>>>(inp, emb);

    // A1 = X @ W_ih1^T + (b_ih1 + b_hh1)
    gemm_nt<<<dim3(32, 32), 256>>>(X, W_ih1, A, ROWS, G4, EMB, bias);

    // layer 1 recurrence
    zero_k<<<128, 256>>>(h, 2 * BATCH * HID);
    zero_k<<<64, 256>>>(c, BATCH * HID);
    for (int s = 0; s < SEQ; s++) {
        float* hin  = h + (s & 1) * BATCH * HID;
        float* hout = h + ((s + 1) & 1) * BATCH * HID;
        lstm_cell<<<128, 256, CELL_SMEM>>>(A + (size_t)s * 16 * G4, W_hh1,
                                           hin, hout, c, h1s + (size_t)s * 16 * HID, HID);
    }

    // A2 = H1 @ W_ih2^T + (b_ih2 + b_hh2)
    gemm_nt<<<dim3(32, 32), 256>>>(h1s, W_ih2, A, ROWS, G4, HID, bias + G4);

    // layer 2 recurrence (writes [B,S,H] layout)
    zero_k<<<128, 256>>>(h, 2 * BATCH * HID);
    zero_k<<<64, 256>>>(c, BATCH * HID);
    for (int s = 0; s < SEQ; s++) {
        float* hin  = h + (s & 1) * BATCH * HID;
        float* hout = h + ((s + 1) & 1) * BATCH * HID;
        lstm_cell<<<128, 256, CELL_SMEM>>>(A + (size_t)s * 16 * G4, W_hh2,
                                           hin, hout, c, h2s + (size_t)s * HID, SEQ * HID);
    }

    // logits = H2 @ W_log^T + b_log
    gemm_nt<<<dim3(250, 32), 256>>>(h2s, W_log, out, ROWS, VOC, HID, b_log);

    // log_softmax
    lse_kernel<<<ROWS, 256>>>(out, lse);
    sub_kernel<<<ROWS * (VOC / 4) / 256, 256>>>(out, lse);
}

// round 10
// speedup vs baseline: 1.0194x; 1.0194x over previous
#include <cuda_runtime.h>
#include <cuda_bf16.h>
#include <cfloat>
#include <math.h>

#define VOC   32000
#define EMB   512
#define HID   1024
#define BATCH 16
#define SEQ   256
#define G4    4096
#define ROWS  4096   // B*S

// ------------------------------- device scratch ---------------------------
__device__ float g_X[ROWS * EMB];
__device__ float g_A[ROWS * G4];
__device__ float g_h1seq[ROWS * HID];   // rows r = s*16+b
__device__ float g_h2seq[ROWS * HID];   // rows r = b*256+s
__device__ float g_h[2 * BATCH * HID];
__device__ float g_c[BATCH * HID];
__device__ float g_lse[ROWS];
__device__ float g_bias[2 * G4];
__device__ int   g_is64;

// ------------------------------- small kernels ----------------------------
__global__ void zero_k(float* p, int n) {
    int i = blockIdx.x * 256 + threadIdx.x;
    if (i < n) p[i] = 0.f;
}

__global__ void detect_i64(const unsigned int* p) {
    __shared__ int any;
    if (threadIdx.x == 0) any = 0;
    __syncthreads();
    int loc = 0;
    for (int i = threadIdx.x; i < 2048; i += 256) loc |= (p[2 * i + 1] != 0u);
    if (loc) atomicOr(&any, 1);
    __syncthreads();
    if (threadIdx.x == 0) g_is64 = (any == 0) ? 1 : 0;
}

__global__ void combine_bias(const float* __restrict__ a1, const float* __restrict__ a2,
                             const float* __restrict__ b1, const float* __restrict__ b2) {
    int i = blockIdx.x * 256 + threadIdx.x;
    if (i < G4) { g_bias[i] = a1[i] + a2[i]; g_bias[G4 + i] = b1[i] + b2[i]; }
}

__global__ void gather_x(const void* __restrict__ inp, const float* __restrict__ emb) {
    int idx4 = blockIdx.x * 256 + threadIdx.x;        // ROWS*128
    if (idx4 >= ROWS * (EMB / 4)) return;
    int r = idx4 >> 7, e4 = idx4 & 127;
    int s = r >> 4, b = r & 15;
    int pos = b * SEQ + s;
    int tok = g_is64 ? (int)((const long long*)inp)[pos] : ((const int*)inp)[pos];
    reinterpret_cast<float4*>(g_X)[idx4] =
        reinterpret_cast<const float4*>(emb)[(size_t)tok * 128 + e4];
}

// ------------------------------- SGEMM NT ---------------------------------
// C[m][n] = sum_k A[m*K+k]*B[n*K+k] + bias[n]; tile 128x128, 8x8/thread
__global__ void __launch_bounds__(256, 2) gemm_nt(
    const float* __restrict__ A, const float* __restrict__ B, float* __restrict__ C,
    int M, int N, int K, const float* __restrict__ bias)
{
    __shared__ __align__(16) float As[16][132];
    __shared__ __align__(16) float Bs[16][132];
    const int tid = threadIdx.x;
    const int n0 = blockIdx.x * 128, m0 = blockIdx.y * 128;
    const int tx = tid & 15, ty = tid >> 4;
    const int lr = tid >> 1, lk = (tid & 1) * 8;

    float acc[8][8];
#pragma unroll
    for (int i = 0; i < 8; i++)
#pragma unroll
        for (int j = 0; j < 8; j++) acc[i][j] = 0.f;

    const float* Ap = A + (size_t)(m0 + lr) * K + lk;
    const float* Bp = B + (size_t)(n0 + lr) * K + lk;

    for (int k0 = 0; k0 < K; k0 += 16) {
        float4 a0 = *reinterpret_cast<const float4*>(Ap + k0);
        float4 a1 = *reinterpret_cast<const float4*>(Ap + k0 + 4);
        float4 b0 = *reinterpret_cast<const float4*>(Bp + k0);
        float4 b1 = *reinterpret_cast<const float4*>(Bp + k0 + 4);
        __syncthreads();
        As[lk+0][lr]=a0.x; As[lk+1][lr]=a0.y; As[lk+2][lr]=a0.z; As[lk+3][lr]=a0.w;
        As[lk+4][lr]=a1.x; As[lk+5][lr]=a1.y; As[lk+6][lr]=a1.z; As[lk+7][lr]=a1.w;
        Bs[lk+0][lr]=b0.x; Bs[lk+1][lr]=b0.y; Bs[lk+2][lr]=b0.z; Bs[lk+3][lr]=b0.w;
        Bs[lk+4][lr]=b1.x; Bs[lk+5][lr]=b1.y; Bs[lk+6][lr]=b1.z; Bs[lk+7][lr]=b1.w;
        __syncthreads();
#pragma unroll
        for (int kk = 0; kk < 16; ++kk) {
            float4 t0 = *reinterpret_cast<const float4*>(&As[kk][ty * 4]);
            float4 t1 = *reinterpret_cast<const float4*>(&As[kk][64 + ty * 4]);
            float4 u0 = *reinterpret_cast<const float4*>(&Bs[kk][tx * 4]);
            float4 u1 = *reinterpret_cast<const float4*>(&Bs[kk][64 + tx * 4]);
            float a[8] = { t0.x,t0.y,t0.z,t0.w, t1.x,t1.y,t1.z,t1.w };
            float b[8] = { u0.x,u0.y,u0.z,u0.w, u1.x,u1.y,u1.z,u1.w };
#pragma unroll
            for (int i = 0; i < 8; i++)
#pragma unroll
                for (int j = 0; j < 8; j++)
                    acc[i][j] = fmaf(a[i], b[j], acc[i][j]);
        }
    }

    float bn[8];
#pragma unroll
    for (int j = 0; j < 8; j++)
        bn[j] = bias ? bias[n0 + (j >> 2) * 64 + tx * 4 + (j & 3)] : 0.f;
#pragma unroll
    for (int i = 0; i < 8; i++) {
        int m = m0 + (i >> 2) * 64 + ty * 4 + (i & 3);
        float4 v0 = make_float4(acc[i][0]+bn[0], acc[i][1]+bn[1], acc[i][2]+bn[2], acc[i][3]+bn[3]);
        float4 v1 = make_float4(acc[i][4]+bn[4], acc[i][5]+bn[5], acc[i][6]+bn[6], acc[i][7]+bn[7]);
        *reinterpret_cast<float4*>(&C[(size_t)m * N + n0 + tx * 4]) = v0;
        *reinterpret_cast<float4*>(&C[(size_t)m * N + n0 + 64 + tx * 4]) = v1;
    }
}

// ------------------------------- LSTM cell --------------------------------
// One (layer, step). CTA owns 8 hidden units (=> 32 Whh rows across 4 gates).
// 256 thr = 8 k-slices x 32 lanes; lane = rg*4+bg; thread does 4 rows x 4
// batches over 128 k; smem tree-reduce; 128-thread pointwise epilogue.
#define H_STRIDE 1028
#define CELL_SMEM ((16 * H_STRIDE + 256 * 16 + 32 * 16) * 4)

__global__ void __launch_bounds__(256) lstm_cell(
    const float* __restrict__ preg, const float* __restrict__ Whh,
    const float* __restrict__ h_in, float* __restrict__ h_out,
    float* __restrict__ c, float* __restrict__ seq_out, int seq_bstride)
{
    extern __shared__ float smem[];
    float* h_sm = smem;                       // 16 * H_STRIDE
    float* red  = smem + 16 * H_STRIDE;       // 256 * 16
    float* g_sm = red + 256 * 16;             // 32 * 16

    const int tid = threadIdx.x, cta = blockIdx.x;

    for (int t = tid; t < BATCH * (HID / 4); t += 256) {
        int b = t >> 8, k4 = t & 255;
        *reinterpret_cast<float4*>(&h_sm[b * H_STRIDE + k4 * 4]) =
            reinterpret_cast<const float4*>(h_in)[b * 256 + k4];
    }
    __syncthreads();

    const int ks = tid >> 5, lane = tid & 31;
    const int rg = lane >> 2, bg = lane & 3;
    const int gate = rg >> 1, jl0 = (rg & 1) * 4;
    const int grow0 = gate * HID + cta * 8 + jl0;

    const float* wp[4];
#pragma unroll
    for (int r = 0; r < 4; r++) wp[r] = Whh + (size_t)(grow0 + r) * HID + ks * 128;
    const float* hq[4];
#pragma unroll
    for (int q = 0; q < 4; q++) hq[q] = &h_sm[(bg + 4 * q) * H_STRIDE + ks * 128];

    float acc[16];
#pragma unroll
    for (int q = 0; q < 16; q++) acc[q] = 0.f;

#pragma unroll 4
    for (int kk = 0; kk < 128; kk += 4) {
        float4 wv[4], hv[4];
#pragma unroll
        for (int r = 0; r < 4; r++) wv[r] = *reinterpret_cast<const float4*>(wp[r] + kk);
#pragma unroll
        for (int q = 0; q < 4; q++) hv[q] = *reinterpret_cast<const float4*>(hq[q] + kk);
#pragma unroll
        for (int r = 0; r < 4; r++)
#pragma unroll
            for (int q = 0; q < 4; q++) {
                float s = acc[r * 4 + q];
                s = fmaf(wv[r].x, hv[q].x, s);
                s = fmaf(wv[r].y, hv[q].y, s);
                s = fmaf(wv[r].z, hv[q].z, s);
                s = fmaf(wv[r].w, hv[q].w, s);
                acc[r * 4 + q] = s;
            }
    }

#pragma unroll
    for (int q = 0; q < 16; q++) red[tid * 16 + q] = acc[q];
    __syncthreads();

    if (tid < 32) {
        int trg = tid >> 2, tbg = tid & 3;
        int tgate = trg >> 1, tjl0 = (trg & 1) * 4;
#pragma unroll
        for (int rr = 0; rr < 4; rr++) {
            int grow = tgate * HID + cta * 8 + tjl0 + rr;
            int lrow = trg * 4 + rr;
#pragma unroll
            for (int bb = 0; bb < 4; bb++) {
                int b = tbg + 4 * bb;
                float sum = 0.f;
#pragma unroll
                for (int p = 0; p < 8; p++) sum += red[(p * 32 + tid) * 16 + rr * 4 + bb];
                g_sm[lrow * 16 + b] = sum + preg[b * G4 + grow];
            }
        }
    }
    __syncthreads();

    if (tid < 128) {
        int jl = tid & 7, b = tid >> 3;
        float iv = g_sm[(0 + jl) * 16 + b];
        float fv = g_sm[(8 + jl) * 16 + b];
        float gv = g_sm[(16 + jl) * 16 + b];
        float ov = g_sm[(24 + jl) * 16 + b];
        int idx = b * HID + cta * 8 + jl;
        float si = 1.f / (1.f + expf(-iv));
        float sf = 1.f / (1.f + expf(-fv));
        float so = 1.f / (1.f + expf(-ov));
        float cn = sf * c[idx] + si * tanhf(gv);
        float hn = so * tanhf(cn);
        c[idx] = cn;
        h_out[idx] = hn;
        seq_out[b * seq_bstride + cta * 8 + jl] = hn;
    }
}

// ------------------------------- log-softmax ------------------------------
__device__ __forceinline__ float fast_exp_neg(float x) {   // x <= 0
    x = fmaxf(x, -87.0f);
    float t = x * 1.4426950408889634f;
    float fl = floorf(t);
    float r = t - fl;
    float p = 1.5403530393381609e-4f;
    p = fmaf(p, r, 1.3333558146428443e-3f);
    p = fmaf(p, r, 9.6181291076284772e-3f);
    p = fmaf(p, r, 5.5504108664821580e-2f);
    p = fmaf(p, r, 2.4022650695910072e-1f);
    p = fmaf(p, r, 6.9314718055994531e-1f);
    p = fmaf(p, r, 1.0f);
    return p * __int_as_float(((int)fl + 127) << 23);
}

__global__ void lse_kernel(const float* __restrict__ logits, float* __restrict__ lse) {
    __shared__ float sm[256], ss[256];
    const int row = blockIdx.x, tid = threadIdx.x;
    const float4* base = reinterpret_cast<const float4*>(logits + (size_t)row * VOC);
    float m = -FLT_MAX, s = 0.f;
    for (int i = tid; i < VOC / 4; i += 256) {
        float4 v = base[i];
        float xs[4] = { v.x, v.y, v.z, v.w };
#pragma unroll
        for (int q = 0; q < 4; q++) {
            float x = xs[q];
            if (x > m) { s = s * fast_exp_neg(m - x) + 1.f; m = x; }
            else       { s += fast_exp_neg(x - m); }
        }
    }
    sm[tid] = m; ss[tid] = s;
    __syncthreads();
    for (int off = 128; off; off >>= 1) {
        if (tid < off) {
            float m1 = sm[tid], s1 = ss[tid], m2 = sm[tid + off], s2 = ss[tid + off];
            float mm = fmaxf(m1, m2);
            ss[tid] = s1 * fast_exp_neg(m1 - mm) + s2 * fast_exp_neg(m2 - mm);
            sm[tid] = mm;
        }
        __syncthreads();
    }
    if (tid == 0) lse[row] = sm[0] + logf(ss[0]);
}

__global__ void sub_kernel(float* __restrict__ out, const float* __restrict__ lse) {
    int idx4 = blockIdx.x * 256 + threadIdx.x;   // ROWS*(VOC/4)
    int row = idx4 / (VOC / 4);
    float l = lse[row];
    float4* p = reinterpret_cast<float4*>(out) + idx4;
    float4 v = *p;
    v.x -= l; v.y -= l; v.z -= l; v.w -= l;
    *p = v;
}

// ------------------------------- launcher ---------------------------------
extern "C" void kernel_launch(void* const* d_in, const int* in_sizes, int n_in,
                              void* d_out, int out_size) {
    (void)in_sizes; (void)n_in; (void)out_size;
    const void*  inp   = d_in[0];
    const float* emb   = (const float*)d_in[1];
    const float* W_ih1 = (const float*)d_in[2];
    const float* W_hh1 = (const float*)d_in[3];
    const float* b_ih1 = (const float*)d_in[4];
    const float* b_hh1 = (const float*)d_in[5];
    const float* W_ih2 = (const float*)d_in[6];
    const float* W_hh2 = (const float*)d_in[7];
    const float* b_ih2 = (const float*)d_in[8];
    const float* b_hh2 = (const float*)d_in[9];
    const float* W_log = (const float*)d_in[10];
    const float* b_log = (const float*)d_in[11];
    float* out = (float*)d_out;

    static bool attr_set = false;
    if (!attr_set) {
        cudaFuncSetAttribute(lstm_cell, cudaFuncAttributeMaxDynamicSharedMemorySize, CELL_SMEM);
        attr_set = true;
    }

    float *X, *A, *h1s, *h2s, *h, *c, *lse;
    cudaGetSymbolAddress((void**)&X,   g_X);
    cudaGetSymbolAddress((void**)&A,   g_A);
    cudaGetSymbolAddress((void**)&h1s, g_h1seq);
    cudaGetSymbolAddress((void**)&h2s, g_h2seq);
    cudaGetSymbolAddress((void**)&h,   g_h);
    cudaGetSymbolAddress((void**)&c,   g_c);
    cudaGetSymbolAddress((void**)&lse, g_lse);
    float* bias;
    cudaGetSymbolAddress((void**)&bias, g_bias);

    detect_i64<<<1, 256>>>((const unsigned int*)inp);
    combine_bias<<<16, 256>>>(b_ih1, b_hh1, b_ih2, b_hh2);
    gather_x<<<2048, 256>>>(inp, emb);

    // A1 = X @ W_ih1^T + (b_ih1 + b_hh1)
    gemm_nt<<<dim3(32, 32), 256>>>(X, W_ih1, A, ROWS, G4, EMB, bias);

    // layer 1 recurrence
    zero_k<<<128, 256>>>(h, 2 * BATCH * HID);
    zero_k<<<64, 256>>>(c, BATCH * HID);
    for (int s = 0; s < SEQ; s++) {
        float* hin  = h + (s & 1) * BATCH * HID;
        float* hout = h + ((s + 1) & 1) * BATCH * HID;
        lstm_cell<<<128, 256, CELL_SMEM>>>(A + (size_t)s * 16 * G4, W_hh1,
                                           hin, hout, c, h1s + (size_t)s * 16 * HID, HID);
    }

    // A2 = H1 @ W_ih2^T + (b_ih2 + b_hh2)
    gemm_nt<<<dim3(32, 32), 256>>>(h1s, W_ih2, A, ROWS, G4, HID, bias + G4);

    // layer 2 recurrence (writes [B,S,H] layout)
    zero_k<<<128, 256>>>(h, 2 * BATCH * HID);
    zero_k<<<64, 256>>>(c, BATCH * HID);
    for (int s = 0; s < SEQ; s++) {
        float* hin  = h + (s & 1) * BATCH * HID;
        float* hout = h + ((s + 1) & 1) * BATCH * HID;
        lstm_cell<<<128, 256, CELL_SMEM>>>(A + (size_t)s * 16 * G4, W_hh2,
                                           hin, hout, c, h2s + (size_t)s * HID, SEQ * HID);
    }

    // logits = H2 @ W_log^T + b_log
    gemm_nt<<<dim3(250, 32), 256>>>(h2s, W_log, out, ROWS, VOC, HID, b_log);

    // log_softmax
    lse_kernel<<<ROWS, 256>>>(out, lse);
    sub_kernel<<<ROWS * (VOC / 4) / 256, 256>>>(out, lse);
}

// round 11
// speedup vs baseline: 1.1122x; 1.0910x over previous
#include <cuda_runtime.h>
#include <cuda_bf16.h>
#include <cfloat>
#include <math.h>

#define VOC   32000
#define EMB   512
#define HID   1024
#define BATCH 16
#define SEQ   256
#define G4    4096
#define ROWS  4096   // B*S
#define NCTA  128

// ------------------------------- device scratch ---------------------------
__device__ float g_X[ROWS * EMB];
__device__ float g_A[ROWS * G4];
__device__ float g_h1seq[ROWS * HID];   // rows r = s*16+b
__device__ float g_h2seq[ROWS * HID];   // rows r = b*256+s
__device__ float g_h[2 * BATCH * HID];
__device__ float g_lse[ROWS];
__device__ float g_bias[2 * G4];
__device__ int   g_is64;
__device__ unsigned g_cnt = 0;
__device__ unsigned g_gen = 0;

// ------------------------------- small kernels ----------------------------
__global__ void zero_k(float* p, int n) {
    int i = blockIdx.x * 256 + threadIdx.x;
    if (i < n) p[i] = 0.f;
}

__global__ void detect_i64(const unsigned int* p) {
    __shared__ int any;
    if (threadIdx.x == 0) any = 0;
    __syncthreads();
    int loc = 0;
    for (int i = threadIdx.x; i < 2048; i += 256) loc |= (p[2 * i + 1] != 0u);
    if (loc) atomicOr(&any, 1);
    __syncthreads();
    if (threadIdx.x == 0) g_is64 = (any == 0) ? 1 : 0;
}

__global__ void combine_bias(const float* __restrict__ a1, const float* __restrict__ a2,
                             const float* __restrict__ b1, const float* __restrict__ b2) {
    int i = blockIdx.x * 256 + threadIdx.x;
    if (i < G4) { g_bias[i] = a1[i] + a2[i]; g_bias[G4 + i] = b1[i] + b2[i]; }
}

__global__ void gather_x(const void* __restrict__ inp, const float* __restrict__ emb) {
    int idx4 = blockIdx.x * 256 + threadIdx.x;        // ROWS*128
    if (idx4 >= ROWS * (EMB / 4)) return;
    int r = idx4 >> 7, e4 = idx4 & 127;
    int s = r >> 4, b = r & 15;
    int pos = b * SEQ + s;
    int tok = g_is64 ? (int)((const long long*)inp)[pos] : ((const int*)inp)[pos];
    reinterpret_cast<float4*>(g_X)[idx4] =
        reinterpret_cast<const float4*>(emb)[(size_t)tok * 128 + e4];
}

// ------------------------------- SGEMM NT (pipelined) ---------------------
// C[m][n] = sum_k A[m*K+k]*B[n*K+k] + bias[n]; 128x128 tile, 8x8/thread,
// next k-slab prefetched into registers during the FMA block.
__global__ void __launch_bounds__(256, 2) gemm_nt(
    const float* __restrict__ A, const float* __restrict__ B, float* __restrict__ C,
    int M, int N, int K, const float* __restrict__ bias)
{
    __shared__ __align__(16) float As[16][132];
    __shared__ __align__(16) float Bs[16][132];
    const int tid = threadIdx.x;
    const int n0 = blockIdx.x * 128, m0 = blockIdx.y * 128;
    const int tx = tid & 15, ty = tid >> 4;
    const int lr = tid >> 1, lk = (tid & 1) * 8;

    float acc[8][8];
#pragma unroll
    for (int i = 0; i < 8; i++)
#pragma unroll
        for (int j = 0; j < 8; j++) acc[i][j] = 0.f;

    const float* Ap = A + (size_t)(m0 + lr) * K + lk;
    const float* Bp = B + (size_t)(n0 + lr) * K + lk;

    float4 a0 = *reinterpret_cast<const float4*>(Ap);
    float4 a1 = *reinterpret_cast<const float4*>(Ap + 4);
    float4 b0 = *reinterpret_cast<const float4*>(Bp);
    float4 b1 = *reinterpret_cast<const float4*>(Bp + 4);
    As[lk+0][lr]=a0.x; As[lk+1][lr]=a0.y; As[lk+2][lr]=a0.z; As[lk+3][lr]=a0.w;
    As[lk+4][lr]=a1.x; As[lk+5][lr]=a1.y; As[lk+6][lr]=a1.z; As[lk+7][lr]=a1.w;
    Bs[lk+0][lr]=b0.x; Bs[lk+1][lr]=b0.y; Bs[lk+2][lr]=b0.z; Bs[lk+3][lr]=b0.w;
    Bs[lk+4][lr]=b1.x; Bs[lk+5][lr]=b1.y; Bs[lk+6][lr]=b1.z; Bs[lk+7][lr]=b1.w;
    __syncthreads();

    for (int k0 = 16; k0 <= K; k0 += 16) {
        bool more = (k0 < K);
        if (more) {
            a0 = *reinterpret_cast<const float4*>(Ap + k0);
            a1 = *reinterpret_cast<const float4*>(Ap + k0 + 4);
            b0 = *reinterpret_cast<const float4*>(Bp + k0);
            b1 = *reinterpret_cast<const float4*>(Bp + k0 + 4);
        }
#pragma unroll
        for (int kk = 0; kk < 16; ++kk) {
            float4 t0 = *reinterpret_cast<const float4*>(&As[kk][ty * 4]);
            float4 t1 = *reinterpret_cast<const float4*>(&As[kk][64 + ty * 4]);
            float4 u0 = *reinterpret_cast<const float4*>(&Bs[kk][tx * 4]);
            float4 u1 = *reinterpret_cast<const float4*>(&Bs[kk][64 + tx * 4]);
            float a[8] = { t0.x,t0.y,t0.z,t0.w, t1.x,t1.y,t1.z,t1.w };
            float b[8] = { u0.x,u0.y,u0.z,u0.w, u1.x,u1.y,u1.z,u1.w };
#pragma unroll
            for (int i = 0; i < 8; i++)
#pragma unroll
                for (int j = 0; j < 8; j++)
                    acc[i][j] = fmaf(a[i], b[j], acc[i][j]);
        }
        if (more) {
            __syncthreads();
            As[lk+0][lr]=a0.x; As[lk+1][lr]=a0.y; As[lk+2][lr]=a0.z; As[lk+3][lr]=a0.w;
            As[lk+4][lr]=a1.x; As[lk+5][lr]=a1.y; As[lk+6][lr]=a1.z; As[lk+7][lr]=a1.w;
            Bs[lk+0][lr]=b0.x; Bs[lk+1][lr]=b0.y; Bs[lk+2][lr]=b0.z; Bs[lk+3][lr]=b0.w;
            Bs[lk+4][lr]=b1.x; Bs[lk+5][lr]=b1.y; Bs[lk+6][lr]=b1.z; Bs[lk+7][lr]=b1.w;
            __syncthreads();
        }
    }

    float bn[8];
#pragma unroll
    for (int j = 0; j < 8; j++)
        bn[j] = bias ? bias[n0 + (j >> 2) * 64 + tx * 4 + (j & 3)] : 0.f;
#pragma unroll
    for (int i = 0; i < 8; i++) {
        int m = m0 + (i >> 2) * 64 + ty * 4 + (i & 3);
        float4 v0 = make_float4(acc[i][0]+bn[0], acc[i][1]+bn[1], acc[i][2]+bn[2], acc[i][3]+bn[3]);
        float4 v1 = make_float4(acc[i][4]+bn[4], acc[i][5]+bn[5], acc[i][6]+bn[6], acc[i][7]+bn[7]);
        *reinterpret_cast<float4*>(&C[(size_t)m * N + n0 + tx * 4]) = v0;
        *reinterpret_cast<float4*>(&C[(size_t)m * N + n0 + 64 + tx * 4]) = v1;
    }
}

// ------------------------------- grid barrier ------------------------------
__device__ __forceinline__ unsigned ld_cg_u32(const unsigned* p) {
    unsigned v;
    asm volatile("ld.global.cg.u32 %0, [%1];" : "=r"(v) : "l"(p));
    return v;
}

__device__ __forceinline__ void grid_barrier() {
    __syncthreads();
    if (threadIdx.x == 0) {
        __threadfence();
        unsigned g = ld_cg_u32(&g_gen);
        if (atomicAdd(&g_cnt, 1u) == NCTA - 1) {
            atomicExch(&g_cnt, 0u);
            __threadfence();
            atomicAdd(&g_gen, 1u);
        } else {
            while (ld_cg_u32(&g_gen) == g) __nanosleep(64);
        }
        __threadfence();
    }
    __syncthreads();
}

// ------------------------------- persistent LSTM layer --------------------
// 128 CTAs (one wave), each owns 8 hidden units for all 256 steps.
// c state lives in SMEM (CTA-private). h ping-pongs in global; staging reads
// via __ldcg (L2-coherent). Whh via __ldg -> L1-resident slice across steps.
#define H_STRIDE 1028
#define CELL_SMEM ((16 * H_STRIDE + 256 * 16 + 32 * 16 + 128) * 4)

__global__ void __launch_bounds__(256) lstm_layer(
    const float* __restrict__ pregA, const float* __restrict__ Whh,
    float* __restrict__ hbuf, float* __restrict__ seq_out,
    int stride_s, int stride_b)
{
    extern __shared__ float smem[];
    float* h_sm = smem;                       // 16 * H_STRIDE
    float* red  = smem + 16 * H_STRIDE;       // 256 * 16
    float* g_sm = red + 256 * 16;             // 32 * 16
    float* c_sm = g_sm + 32 * 16;             // 128

    const int tid = threadIdx.x, cta = blockIdx.x;
    if (tid < 128) c_sm[tid] = 0.f;

    const int ks = tid >> 5, lane = tid & 31;
    const int rg = lane >> 2, bg = lane & 3;
    const int gate = rg >> 1, jl0 = (rg & 1) * 4;
    const int grow0 = gate * HID + cta * 8 + jl0;

    const float* wp[4];
#pragma unroll
    for (int r = 0; r < 4; r++) wp[r] = Whh + (size_t)(grow0 + r) * HID + ks * 128;

    for (int s = 0; s < SEQ; s++) {
        const float* h_in  = hbuf + (s & 1) * (BATCH * HID);
        float*       h_out = hbuf + ((s + 1) & 1) * (BATCH * HID);
        const float* preg  = pregA + (size_t)s * 16 * G4;

        // stage h (L2-coherent loads; other SMs wrote it last step)
        for (int t = tid; t < BATCH * (HID / 4); t += 256) {
            int b = t >> 8, k4 = t & 255;
            float4 v = __ldcg(reinterpret_cast<const float4*>(h_in) + b * 256 + k4);
            *reinterpret_cast<float4*>(&h_sm[b * H_STRIDE + k4 * 4]) = v;
        }
        __syncthreads();

        const float* hq[4];
#pragma unroll
        for (int q = 0; q < 4; q++) hq[q] = &h_sm[(bg + 4 * q) * H_STRIDE + ks * 128];

        float acc[16];
#pragma unroll
        for (int q = 0; q < 16; q++) acc[q] = 0.f;

#pragma unroll 4
        for (int kk = 0; kk < 128; kk += 4) {
            float4 wv[4], hv[4];
#pragma unroll
            for (int r = 0; r < 4; r++)
                wv[r] = __ldg(reinterpret_cast<const float4*>(wp[r] + kk));
#pragma unroll
            for (int q = 0; q < 4; q++)
                hv[q] = *reinterpret_cast<const float4*>(hq[q] + kk);
#pragma unroll
            for (int r = 0; r < 4; r++)
#pragma unroll
                for (int q = 0; q < 4; q++) {
                    float v = acc[r * 4 + q];
                    v = fmaf(wv[r].x, hv[q].x, v);
                    v = fmaf(wv[r].y, hv[q].y, v);
                    v = fmaf(wv[r].z, hv[q].z, v);
                    v = fmaf(wv[r].w, hv[q].w, v);
                    acc[r * 4 + q] = v;
                }
        }

#pragma unroll
        for (int q = 0; q < 16; q++) red[tid * 16 + q] = acc[q];
        __syncthreads();

        if (tid < 32) {
            int trg = tid >> 2, tbg = tid & 3;
            int tgate = trg >> 1, tjl0 = (trg & 1) * 4;
#pragma unroll
            for (int rr = 0; rr < 4; rr++) {
                int grow = tgate * HID + cta * 8 + tjl0 + rr;
                int lrow = trg * 4 + rr;
#pragma unroll
                for (int bb = 0; bb < 4; bb++) {
                    int b = tbg + 4 * bb;
                    float sum = 0.f;
#pragma unroll
                    for (int p = 0; p < 8; p++) sum += red[(p * 32 + tid) * 16 + rr * 4 + bb];
                    g_sm[lrow * 16 + b] = sum + preg[b * G4 + grow];
                }
            }
        }
        __syncthreads();

        if (tid < 128) {
            int jl = tid & 7, b = tid >> 3;
            float iv = g_sm[(0  + jl) * 16 + b];
            float fv = g_sm[(8  + jl) * 16 + b];
            float gv = g_sm[(16 + jl) * 16 + b];
            float ov = g_sm[(24 + jl) * 16 + b];
            float si = 1.f / (1.f + expf(-iv));
            float sf = 1.f / (1.f + expf(-fv));
            float so = 1.f / (1.f + expf(-ov));
            float cn = sf * c_sm[tid] + si * tanhf(gv);
            float hn = so * tanhf(cn);
            c_sm[tid] = cn;
            h_out[b * HID + cta * 8 + jl] = hn;
            seq_out[(size_t)s * stride_s + (size_t)b * stride_b + cta * 8 + jl] = hn;
        }
        grid_barrier();
    }
}

// ------------------------------- log-softmax ------------------------------
__device__ __forceinline__ float fast_exp_neg(float x) {   // x <= 0
    x = fmaxf(x, -87.0f);
    float t = x * 1.4426950408889634f;
    float fl = floorf(t);
    float r = t - fl;
    float p = 1.5403530393381609e-4f;
    p = fmaf(p, r, 1.3333558146428443e-3f);
    p = fmaf(p, r, 9.6181291076284772e-3f);
    p = fmaf(p, r, 5.5504108664821580e-2f);
    p = fmaf(p, r, 2.4022650695910072e-1f);
    p = fmaf(p, r, 6.9314718055994531e-1f);
    p = fmaf(p, r, 1.0f);
    return p * __int_as_float(((int)fl + 127) << 23);
}

__global__ void lse_kernel(const float* __restrict__ logits, float* __restrict__ lse) {
    __shared__ float sm[256], ss[256];
    const int row = blockIdx.x, tid = threadIdx.x;
    const float4* base = reinterpret_cast<const float4*>(logits + (size_t)row * VOC);
    float m = -FLT_MAX, s = 0.f;
    for (int i = tid; i < VOC / 4; i += 256) {
        float4 v = base[i];
        float xs[4] = { v.x, v.y, v.z, v.w };
#pragma unroll
        for (int q = 0; q < 4; q++) {
            float x = xs[q];
            if (x > m) { s = s * fast_exp_neg(m - x) + 1.f; m = x; }
            else       { s += fast_exp_neg(x - m); }
        }
    }
    sm[tid] = m; ss[tid] = s;
    __syncthreads();
    for (int off = 128; off; off >>= 1) {
        if (tid < off) {
            float m1 = sm[tid], s1 = ss[tid], m2 = sm[tid + off], s2 = ss[tid + off];
            float mm = fmaxf(m1, m2);
            ss[tid] = s1 * fast_exp_neg(m1 - mm) + s2 * fast_exp_neg(m2 - mm);
            sm[tid] = mm;
        }
        __syncthreads();
    }
    if (tid == 0) lse[row] = sm[0] + logf(ss[0]);
}

__global__ void sub_kernel(float* __restrict__ out, const float* __restrict__ lse) {
    int idx4 = blockIdx.x * 256 + threadIdx.x;   // ROWS*(VOC/4)
    int row = idx4 / (VOC / 4);
    float l = lse[row];
    float4* p = reinterpret_cast<float4*>(out) + idx4;
    float4 v = *p;
    v.x -= l; v.y -= l; v.z -= l; v.w -= l;
    *p = v;
}

// ------------------------------- launcher ---------------------------------
extern "C" void kernel_launch(void* const* d_in, const int* in_sizes, int n_in,
                              void* d_out, int out_size) {
    (void)in_sizes; (void)n_in; (void)out_size;
    const void*  inp   = d_in[0];
    const float* emb   = (const float*)d_in[1];
    const float* W_ih1 = (const float*)d_in[2];
    const float* W_hh1 = (const float*)d_in[3];
    const float* b_ih1 = (const float*)d_in[4];
    const float* b_hh1 = (const float*)d_in[5];
    const float* W_ih2 = (const float*)d_in[6];
    const float* W_hh2 = (const float*)d_in[7];
    const float* b_ih2 = (const float*)d_in[8];
    const float* b_hh2 = (const float*)d_in[9];
    const float* W_log = (const float*)d_in[10];
    const float* b_log = (const float*)d_in[11];
    float* out = (float*)d_out;

    static bool attr_set = false;
    if (!attr_set) {
        cudaFuncSetAttribute(lstm_layer, cudaFuncAttributeMaxDynamicSharedMemorySize, CELL_SMEM);
        attr_set = true;
    }

    float *X, *A, *h1s, *h2s, *h, *lse, *bias;
    cudaGetSymbolAddress((void**)&X,    g_X);
    cudaGetSymbolAddress((void**)&A,    g_A);
    cudaGetSymbolAddress((void**)&h1s,  g_h1seq);
    cudaGetSymbolAddress((void**)&h2s,  g_h2seq);
    cudaGetSymbolAddress((void**)&h,    g_h);
    cudaGetSymbolAddress((void**)&lse,  g_lse);
    cudaGetSymbolAddress((void**)&bias, g_bias);

    detect_i64<<<1, 256>>>((const unsigned int*)inp);
    combine_bias<<<16, 256>>>(b_ih1, b_hh1, b_ih2, b_hh2);
    gather_x<<<2048, 256>>>(inp, emb);

    // A1 = X @ W_ih1^T + (b_ih1 + b_hh1)
    gemm_nt<<<dim3(32, 32), 256>>>(X, W_ih1, A, ROWS, G4, EMB, bias);

    // layer 1 recurrence (persistent, seq layout rows r = s*16+b)
    zero_k<<<64, 256>>>(h, BATCH * HID);
    lstm_layer<<<NCTA, 256, CELL_SMEM>>>(A, W_hh1, h, h1s, 16 * HID, HID);

    // A2 = H1 @ W_ih2^T + (b_ih2 + b_hh2)
    gemm_nt<<<dim3(32, 32), 256>>>(h1s, W_ih2, A, ROWS, G4, HID, bias + G4);

    // layer 2 recurrence (persistent, writes [B,S,H] layout)
    zero_k<<<64, 256>>>(h, BATCH * HID);
    lstm_layer<<<NCTA, 256, CELL_SMEM>>>(A, W_hh2, h, h2s, HID, SEQ * HID);

    // logits = H2 @ W_log^T + b_log
    gemm_nt<<<dim3(250, 32), 256>>>(h2s, W_log, out, ROWS, VOC, HID, b_log);

    // log_softmax
    lse_kernel<<<ROWS, 256>>>(out, lse);
    sub_kernel<<<ROWS * (VOC / 4) / 256, 256>>>(out, lse);
}